// round 15
// baseline (speedup 1.0000x reference)
#include <cuda_runtime.h>
#include <cuda_bf16.h>
#include <math.h>

#define R 512
#define K 81
#define SCORE_THRESH 0.001f
#define MAX_PER_IMG 100
#define POST_NMS_TOPN 300
#define XFORM_CLIP 4.135166556742356f  /* log(1000/16) */
#define IM_W_M1 1332.0f
#define IM_H_M1 799.0f
#define TRI_TOTAL 4352                 /* sum_{w=0}^{15} 32*(w+1) */
#define NCLS 80                        /* classes 1..80 (class 0 always invalid) */
#define GRID 296                       /* 2 blocks/SM target (flags stay safe if not) */
#define ITEMS (NCLS * TRI_TOTAL)
#define CHUNK ((ITEMS + GRID - 1) / GRID)

// ---- global scratch (zero-init at load; flags/counters reset by finalize) ----
__device__ unsigned           g_ready[NCLS];    // sort-done flag per class
__device__ unsigned           g_maskcnt[NCLS];  // mask words completed per class
__device__ unsigned           g_done;           // scan ticket (self-resetting)
__device__ unsigned long long g_rowkey[R];      // per-row argmax accum (self-resetting)
__device__ unsigned long long g_skeyG[NCLS * R];
__device__ float4             g_sboxG[NCLS * R];
__device__ float              g_sareaG[NCLS * R];
__device__ unsigned           g_maskG[NCLS * R * 16];

// ---------------------------------------------------------------------------
__device__ __forceinline__ float4 xform_box(const float* __restrict__ rois,
                                            const float* __restrict__ deltas,
                                            int r, int k) {
    float4 roi = reinterpret_cast<const float4*>(rois)[r];
    float4 dl  = *reinterpret_cast<const float4*>(deltas + r * (4 * K) + 4 * k);

    float w  = roi.z - roi.x + 1.0f;
    float h  = roi.w - roi.y + 1.0f;
    float cx = roi.x + 0.5f * w;
    float cy = roi.y + 0.5f * h;

    float dx = dl.x / 10.0f;
    float dy = dl.y / 10.0f;
    float dw = fminf(dl.z / 5.0f, XFORM_CLIP);
    float dh = fminf(dl.w / 5.0f, XFORM_CLIP);

    float pcx = dx * w + cx;
    float pcy = dy * h + cy;
    float pw  = expf(dw) * w;
    float ph  = expf(dh) * h;

    float ox1 = fminf(fmaxf(pcx - 0.5f * pw, 0.0f), IM_W_M1);
    float oy1 = fminf(fmaxf(pcy - 0.5f * ph, 0.0f), IM_H_M1);
    float ox2 = fminf(fmaxf(pcx + 0.5f * pw - 1.0f, 0.0f), IM_W_M1);
    float oy2 = fminf(fmaxf(pcy + 0.5f * ph - 1.0f, 0.0f), IM_H_M1);
    return make_float4(ox1, oy1, ox2, oy2);
}

// ---------------------------------------------------------------------------
__device__ __forceinline__ unsigned long long cswap_shfl(unsigned long long key,
                                                         int tid, int kk, int j) {
    unsigned long long pk = __shfl_xor_sync(0xffffffffu, key, j);
    bool asc   = ((tid & kk) == 0);
    bool lower = ((tid & j) == 0);
    bool cmp   = key > pk;
    bool take  = ((cmp == asc) == lower);
    return take ? pk : key;
}

__device__ __forceinline__ void sort512(unsigned long long* skey, int tid) {
    unsigned long long key = skey[tid];
#pragma unroll
    for (int kk = 2; kk <= 32; kk <<= 1)
#pragma unroll
        for (int j = kk >> 1; j > 0; j >>= 1)
            key = cswap_shfl(key, tid, kk, j);
    skey[tid] = key;
    __syncthreads();
#pragma unroll
    for (int kk = 64; kk <= 512; kk <<= 1) {
        for (int j = kk >> 1; j >= 32; j >>= 1) {
            int ixj = tid ^ j;
            if (ixj > tid) {
                bool up = ((tid & kk) == 0);
                unsigned long long a = skey[tid], b = skey[ixj];
                if ((a > b) == up) { skey[tid] = b; skey[ixj] = a; }
            }
            __syncthreads();
        }
        key = skey[tid];
#pragma unroll
        for (int j = 16; j > 0; j >>= 1)
            key = cswap_shfl(key, tid, kk, j);
        skey[tid] = key;
        __syncthreads();
    }
}

// ---------------------------------------------------------------------------
__global__ __launch_bounds__(R, 2) void detect_kernel(const float* __restrict__ rois,
                                                      const float* __restrict__ deltas,
                                                      const float* __restrict__ scores,
                                                      float* __restrict__ out,
                                                      int out_size) {
    const int bid = blockIdx.x;
    const int tid = threadIdx.x;

    // 16B alignment REQUIRED: smask head aliased as float4*.
    __shared__ __align__(16) unsigned smask[R * 16];   // 32 KB
    __shared__ unsigned long long skey[R];             // 4 KB
    __shared__ float4 sboxS[R];                        // 8 KB
    __shared__ float  sareaS[R];                       // 2 KB
    __shared__ unsigned skeepw[16];
    __shared__ int s_isLast;
    float4* sboxO  = reinterpret_cast<float4*>(smask);            // 8 KB alias
    float*  sareaO = reinterpret_cast<float*>(smask + 2048 * 2);  // alias @16KB

    unsigned long long myKey = 0;   // this thread's sorted key (bid<80 only)

    // ---------------- Phase A: per-class transform + sort ----------------
    if (bid < NCLS) {
        const int c = bid + 1;
        float4 b = xform_box(rois, deltas, tid, c);
        sboxO[tid]  = b;
        sareaO[tid] = (b.z - b.x + 1.0f) * (b.w - b.y + 1.0f);
        unsigned sb = __float_as_uint(scores[tid * K + c]);
        skey[tid] = ((unsigned long long)(~sb) << 32) | (unsigned)tid;
        __syncthreads();

        sort512(skey, tid);

        myKey = skey[tid];
        int oi = (unsigned)myKey;
        g_skeyG[bid * R + tid]  = myKey;
        g_sboxG[bid * R + tid]  = sboxO[oi];
        g_sareaG[bid * R + tid] = sareaO[oi];

        __syncthreads();                    // all global writes issued
        if (tid == 0) {
            __threadfence();                // publish sorted data
            atomicExch(&g_ready[bid], 1u);  // flag: class bid sorted
        }
    }

    // ---------------- Phase B: masks, flat-partitioned, flag-gated --------
    {
        int fstart = bid * CHUNK;
        int fend   = min(fstart + CHUNK, ITEMS);
        int c0 = fstart / TRI_TOTAL;
        int c1 = (fend - 1) / TRI_TOTAL;
        for (int cls = c0; cls <= c1; ++cls) {
            // wait for this class's sorted data (producer never blocks first)
            if (tid == 0) {
                while (*(volatile unsigned*)&g_ready[cls] == 0u) __nanosleep(32);
                __threadfence();            // acquire
            }
            __syncthreads();                // also protects staging buffers
            sboxS[tid]  = g_sboxG[cls * R + tid];
            sareaS[tid] = g_sareaG[cls * R + tid];
            __syncthreads();

            int s0 = max(fstart, cls * TRI_TOTAL);
            int s1 = min(fend, (cls + 1) * TRI_TOTAL);
            for (int f = s0 + tid; f < s1; f += R) {
                int fl = f - cls * TRI_TOTAL;
                int w = (int)((sqrtf(1.0f + (float)fl * 0.25f) - 1.0f) * 0.5f);
                while (16 * (w + 1) * (w + 2) <= fl) ++w;
                while (16 * w * (w + 1) > fl) --w;
                int i = fl - 16 * w * (w + 1);

                float4 bi = sboxS[i];
                float  ai = sareaS[i];
                unsigned bits = 0;
#pragma unroll
                for (int b = 0; b < 32; ++b) {
                    int j = (w << 5) | b;
                    float4 bj = sboxS[j];            // broadcast across warp
                    float  aj = sareaS[j];
                    float xx1 = fmaxf(bi.x, bj.x);
                    float yy1 = fmaxf(bi.y, bj.y);
                    float xx2 = fminf(bi.z, bj.z);
                    float yy2 = fminf(bi.w, bj.w);
                    float iw = fmaxf(xx2 - xx1 + 1.0f, 0.0f);
                    float ih = fmaxf(yy2 - yy1 + 1.0f, 0.0f);
                    float inter = iw * ih;
                    float uni = ai + aj - inter;     // > 0 always
                    if (inter + inter > uni) bits |= (1u << b);   // iou > 0.5
                }
                g_maskG[cls * (R * 16) + i * 16 + w] = bits;
            }
            __syncthreads();                // all this block's words written
            if (tid == 0) {
                __threadfence();            // publish mask words
                atomicAdd(&g_maskcnt[cls], (unsigned)(s1 - s0));
            }
        }
    }
    if (bid >= NCLS) return;

    // ---------------- Phase C: wait for own class, stage, scan ------------
    if (tid == 0) {
        while (*(volatile unsigned*)&g_maskcnt[bid] != (unsigned)TRI_TOTAL)
            __nanosleep(32);
        __threadfence();                    // acquire
    }
    __syncthreads();

    {
        const uint4* src = reinterpret_cast<const uint4*>(g_maskG + bid * (R * 16));
        uint4* dst = reinterpret_cast<uint4*>(smask);
        for (int i = tid; i < R * 4; i += R) dst[i] = src[i];
        skey[tid] = myKey;                  // kept in register since Phase A
    }
    __syncthreads();

    // Greedy scan, chunked. Lane w (<16) owns removal word w.
    // Chain uses forward-masked diagonal ORs so kwc = ~remv afterwards:
    // bits <= j of diag[j] were never consulted by the original recurrence,
    // so masking them is bit-equivalent and keeps word ch clean.
    if (tid < 32) {
        const int lane = tid;
        unsigned remv = 0, kw = 0;
        for (int ch = 0; ch < 16; ++ch) {
            unsigned kwc = 0;
            if (lane == ch) {
                unsigned diag[32];
#pragma unroll
                for (int j = 0; j < 32; ++j)
                    diag[j] = smask[(ch * 32 + j) * 16 + ch];
#pragma unroll
                for (int j = 0; j < 32; ++j) {
                    unsigned s = (unsigned)(((int)(remv << (31 - j))) >> 31);
                    remv |= diag[j] & ~s & (0xFFFFFFFEu << j);
                }
                kwc = ~remv;                // live set of this chunk
                kw = kwc;
            }
            kwc = __shfl_sync(0xffffffffu, kwc, ch);
            if (lane > ch && lane < 16) {
#pragma unroll
                for (int j = 0; j < 32; ++j) {
                    unsigned live = (unsigned)(((int)(kwc << (31 - j))) >> 31);
                    remv |= smask[(ch * 32 + j) * 16 + lane] & live;
                }
            }
        }
        // POST_NMS_TOPN clamp: keep first 300 kept (sorted order)
        int cnt = (lane < 16) ? __popc(kw) : 0;
        int incl = cnt;
        for (int off = 1; off < 16; off <<= 1) {
            int v = __shfl_up_sync(0xffffffffu, incl, off);
            if (lane >= off) incl += v;
        }
        int excl = incl - cnt;
        if (lane < 16) {
            if (excl >= POST_NMS_TOPN) {
                kw = 0;
            } else if (excl + cnt > POST_NMS_TOPN) {
                int allowed = POST_NMS_TOPN - excl;
                while (cnt > allowed) {
                    int hb = 31 - __clz(kw);
                    kw &= ~(1u << hb);
                    --cnt;
                }
            }
            skeepw[lane] = kw;
        }
    }
    __syncthreads();

    // validity + per-row argmax accumulation (exact, first-occurrence ties)
    {
        const int c = bid + 1;
        float maxsc = __uint_as_float(~(unsigned)(skey[0] >> 32));
        bool cvalid = maxsc > SCORE_THRESH;
        unsigned long long kk = skey[tid];
        bool kept = (skeepw[tid >> 5] >> (tid & 31)) & 1u;
        if (cvalid && kept) {
            unsigned sb = ~(unsigned)(kk >> 32);
            int orig = (unsigned)kk;
            atomicMax(&g_rowkey[orig],
                      ((unsigned long long)sb << 32) | (unsigned)(K - c));
        }
    }

    // completion ticket; last scan block inlines the finalize
    __threadfence();
    __syncthreads();
    if (tid == 0) {
        unsigned ticket = atomicAdd(&g_done, 1u);
        s_isLast = (ticket == NCLS - 1);
        if (s_isLast) g_done = 0;
    }
    __syncthreads();
    if (!s_isLast) return;

    // ---- Inline finalize (runs after ALL flag/counter reads: safe resets) ----
    if (tid < NCLS) { g_ready[tid] = 0u; g_maskcnt[tid] = 0u; }

    int* flabel = reinterpret_cast<int*>(smask);
    {
        unsigned long long kv = atomicExch(&g_rowkey[tid], 0ULL);
        unsigned sb = (unsigned)(kv >> 32);
        flabel[tid] = kv ? (K - (int)(kv & 0xffffffffu)) : 0;
        skey[tid] = ((unsigned long long)(~sb) << 32) | (unsigned)tid;
    }
    __syncthreads();

    sort512(skey, tid);

    if (tid < MAX_PER_IMG) {
        unsigned long long kk = skey[tid];
        int top = (unsigned)kk;
        float sc = __uint_as_float(~(unsigned)(kk >> 32));
        int lab = flabel[top];
        bool valid = sc > SCORE_THRESH;
        float4 b = xform_box(rois, deltas, top, lab);

        float osc = valid ? sc : 0.0f;
        float bx1 = valid ? b.x : 0.0f;
        float by1 = valid ? b.y : 0.0f;
        float bx2 = valid ? b.z : 0.0f;
        float by2 = valid ? b.w : 0.0f;

        int base = tid * 5;
        if (base + 4 < out_size) {
            out[base + 0] = osc;
            out[base + 1] = bx1;
            out[base + 2] = by1;
            out[base + 3] = bx2;
            out[base + 4] = by2;
        }
        if (MAX_PER_IMG * 5 + tid < out_size) out[MAX_PER_IMG * 5 + tid] = (float)lab;
        if (MAX_PER_IMG * 6 + tid < out_size) out[MAX_PER_IMG * 6 + tid] = (float)top;
    }
}

// ---------------------------------------------------------------------------
extern "C" void kernel_launch(void* const* d_in, const int* in_sizes, int n_in,
                              void* d_out, int out_size) {
    const float* rois   = (const float*)d_in[0];
    const float* deltas = (const float*)d_in[1];
    const float* scores = (const float*)d_in[2];
    float* out = (float*)d_out;
    (void)in_sizes; (void)n_in;

    detect_kernel<<<GRID, R>>>(rois, deltas, scores, out, out_size);
}

// round 16
// speedup vs baseline: 1.4065x; 1.4065x over previous
#include <cuda_runtime.h>
#include <cuda_bf16.h>
#include <math.h>

#define R 512
#define K 81
#define SCORE_THRESH 0.001f
#define MAX_PER_IMG 100
#define POST_NMS_TOPN 300
#define XFORM_CLIP 4.135166556742356f  /* log(1000/16) */
#define IM_W_M1 1332.0f
#define IM_H_M1 799.0f
#define NCLS 80                        /* classes 1..80 (class 0 always invalid) */

// ---- global scratch (zero-init at load; all self-resetting per launch) ----
__device__ unsigned           g_done;       // finalize ticket
__device__ unsigned long long g_rowkey[R]; // per-row argmax accumulator

// ---------------------------------------------------------------------------
__device__ __forceinline__ float4 xform_box(const float* __restrict__ rois,
                                            const float* __restrict__ deltas,
                                            int r, int k) {
    float4 roi = reinterpret_cast<const float4*>(rois)[r];
    float4 dl  = *reinterpret_cast<const float4*>(deltas + r * (4 * K) + 4 * k);

    float w  = roi.z - roi.x + 1.0f;
    float h  = roi.w - roi.y + 1.0f;
    float cx = roi.x + 0.5f * w;
    float cy = roi.y + 0.5f * h;

    float dx = dl.x / 10.0f;
    float dy = dl.y / 10.0f;
    float dw = fminf(dl.z / 5.0f, XFORM_CLIP);
    float dh = fminf(dl.w / 5.0f, XFORM_CLIP);

    float pcx = dx * w + cx;
    float pcy = dy * h + cy;
    float pw  = expf(dw) * w;
    float ph  = expf(dh) * h;

    float ox1 = fminf(fmaxf(pcx - 0.5f * pw, 0.0f), IM_W_M1);
    float oy1 = fminf(fmaxf(pcy - 0.5f * ph, 0.0f), IM_H_M1);
    float ox2 = fminf(fmaxf(pcx + 0.5f * pw - 1.0f, 0.0f), IM_W_M1);
    float oy2 = fminf(fmaxf(pcy + 0.5f * ph - 1.0f, 0.0f), IM_H_M1);
    return make_float4(ox1, oy1, ox2, oy2);
}

// ---------------------------------------------------------------------------
__device__ __forceinline__ unsigned long long cswap_shfl(unsigned long long key,
                                                         int tid, int kk, int j) {
    unsigned long long pk = __shfl_xor_sync(0xffffffffu, key, j);
    bool asc   = ((tid & kk) == 0);
    bool lower = ((tid & j) == 0);
    bool cmp   = key > pk;
    bool take  = ((cmp == asc) == lower);
    return take ? pk : key;
}

__device__ __forceinline__ void sort512(unsigned long long* skey, int tid) {
    unsigned long long key = skey[tid];
#pragma unroll
    for (int kk = 2; kk <= 32; kk <<= 1)
#pragma unroll
        for (int j = kk >> 1; j > 0; j >>= 1)
            key = cswap_shfl(key, tid, kk, j);
    skey[tid] = key;
    __syncthreads();
#pragma unroll
    for (int kk = 64; kk <= 512; kk <<= 1) {
        for (int j = kk >> 1; j >= 32; j >>= 1) {
            int ixj = tid ^ j;
            if (ixj > tid) {
                bool up = ((tid & kk) == 0);
                unsigned long long a = skey[tid], b = skey[ixj];
                if ((a > b) == up) { skey[tid] = b; skey[ixj] = a; }
            }
            __syncthreads();
        }
        key = skey[tid];
#pragma unroll
        for (int j = 16; j > 0; j >>= 1)
            key = cswap_shfl(key, tid, kk, j);
        skey[tid] = key;
        __syncthreads();
    }
}

// ---------------------------------------------------------------------------
// One block per class, 512 threads. Warp-specialized mask/scan overlap:
//   warps 1..15: produce suppression mask row-chunk by row-chunk
//   warp 0:      greedy-scan chunk ch as soon as its 15 producer arrivals land
// ---------------------------------------------------------------------------
__global__ __launch_bounds__(R, 1) void detect_kernel(const float* __restrict__ rois,
                                                      const float* __restrict__ deltas,
                                                      const float* __restrict__ scores,
                                                      float* __restrict__ out,
                                                      int out_size) {
    const int c   = blockIdx.x + 1;
    const int tid = threadIdx.x;

    // 16B alignment REQUIRED: smask head aliased as float4*.
    __shared__ __align__(16) unsigned smask[R * 16];   // 32 KB
    __shared__ unsigned long long skey[R];             // 4 KB
    __shared__ float4 sboxS[R];                        // 8 KB  sorted-order boxes
    __shared__ float  sareaS[R];                       // 2 KB  sorted-order areas
    __shared__ unsigned skeepw[16];
    __shared__ unsigned s_arrive[16];                  // per-chunk producer arrivals
    __shared__ int s_isLast;
    float4* sboxO  = reinterpret_cast<float4*>(smask);            // 8 KB alias
    float*  sareaO = reinterpret_cast<float*>(smask + 2048 * 2);  // alias @16KB

    // Phase 1: box + stable sort key for this row
    {
        float4 b = xform_box(rois, deltas, tid, c);
        sboxO[tid]  = b;
        sareaO[tid] = (b.z - b.x + 1.0f) * (b.w - b.y + 1.0f);
        unsigned sb = __float_as_uint(scores[tid * K + c]);
        skey[tid] = ((unsigned long long)(~sb) << 32) | (unsigned)tid;
    }
    __syncthreads();

    // Phase 2: sort (ascending uint64 => score desc, idx asc)
    sort512(skey, tid);

    // Phase 3: gather boxes into sorted order, republish
    {
        int oi = (unsigned)skey[tid];
        float4 bi = sboxO[oi];
        float  ai = sareaO[oi];
        __syncthreads();                 // gathers done before alias reuse
        sboxS[tid]  = bi;
        sareaS[tid] = ai;
        if (tid < 16) s_arrive[tid] = 0u;
    }
    __syncthreads();

    // Phase 4+5 overlapped: producers (warps 1-15) & scanner (warp 0)
    const int wid  = tid >> 5;
    const int lane = tid & 31;

    if (wid != 0) {
        // ---------------- producers: chunk-ordered mask ----------------
        const int q = wid - 1;                    // 0..14
        for (int ch = 0; ch < 16; ++ch) {
            const float4 bi = sboxS[ch * 32 + lane];
            const float  ai = sareaS[ch * 32 + lane];
            for (int w = ch + q; w < 16; w += 15) {
                unsigned bits = 0;
#pragma unroll
                for (int b = 0; b < 32; ++b) {
                    int j = (w << 5) | b;
                    float4 bj = sboxS[j];            // broadcast across warp
                    float  aj = sareaS[j];
                    float xx1 = fmaxf(bi.x, bj.x);
                    float yy1 = fmaxf(bi.y, bj.y);
                    float xx2 = fminf(bi.z, bj.z);
                    float yy2 = fminf(bi.w, bj.w);
                    float iw = fmaxf(xx2 - xx1 + 1.0f, 0.0f);
                    float ih = fmaxf(yy2 - yy1 + 1.0f, 0.0f);
                    float inter = iw * ih;
                    float uni = ai + aj - inter;     // > 0 always
                    if (inter + inter > uni) bits |= (1u << b);   // iou > 0.5
                }
                smask[(ch * 32 + lane) * 16 + w] = bits;
            }
            __threadfence_block();                   // publish chunk words
            if (lane == 0) atomicAdd(&s_arrive[ch], 1u);
        }
    } else {
        // ---------------- scanner: greedy scan, chunk-gated -------------
        unsigned remv = 0, kw = 0;
        for (int ch = 0; ch < 16; ++ch) {
            if (lane == 0) {
                while (*(volatile unsigned*)&s_arrive[ch] < 15u) __nanosleep(32);
            }
            __syncwarp();
            __threadfence_block();                   // acquire chunk words

            unsigned kwc = 0;
            if (lane == ch) {
                unsigned diag[32];
#pragma unroll
                for (int j = 0; j < 32; ++j)
                    diag[j] = smask[(ch * 32 + j) * 16 + ch];
#pragma unroll
                for (int j = 0; j < 32; ++j) {
                    unsigned s = (unsigned)(((int)(remv << (31 - j))) >> 31);
                    remv |= diag[j] & ~s & (0xFFFFFFFEu << j);
                }
                kwc = ~remv;                // live set of this chunk
                kw = kwc;
            }
            kwc = __shfl_sync(0xffffffffu, kwc, ch);
            if (lane > ch && lane < 16) {
#pragma unroll
                for (int j = 0; j < 32; ++j) {
                    unsigned live = (unsigned)(((int)(kwc << (31 - j))) >> 31);
                    remv |= smask[(ch * 32 + j) * 16 + lane] & live;
                }
            }
        }
        // POST_NMS_TOPN clamp: keep first 300 kept (sorted order)
        int cnt = (lane < 16) ? __popc(kw) : 0;
        int incl = cnt;
        for (int off = 1; off < 16; off <<= 1) {
            int v = __shfl_up_sync(0xffffffffu, incl, off);
            if (lane >= off) incl += v;
        }
        int excl = incl - cnt;
        if (lane < 16) {
            if (excl >= POST_NMS_TOPN) {
                kw = 0;
            } else if (excl + cnt > POST_NMS_TOPN) {
                int allowed = POST_NMS_TOPN - excl;
                while (cnt > allowed) {
                    int hb = 31 - __clz(kw);
                    kw &= ~(1u << hb);
                    --cnt;
                }
            }
            skeepw[lane] = kw;
        }
    }
    __syncthreads();

    // Phase 6: class validity + per-row argmax accumulation.
    // key = score_bits<<32 | (K - c): max => highest score, ties => smallest
    // class = first-occurrence argmax. Bit-exact score carried through.
    {
        float maxsc = __uint_as_float(~(unsigned)(skey[0] >> 32));
        bool cvalid = maxsc > SCORE_THRESH;          // c >= 1 by construction
        unsigned long long kk = skey[tid];
        bool kept = (skeepw[tid >> 5] >> (tid & 31)) & 1u;
        if (cvalid && kept) {
            unsigned sb = ~(unsigned)(kk >> 32);     // raw score bits (> 0)
            int orig = (unsigned)kk;
            atomicMax(&g_rowkey[orig],
                      ((unsigned long long)sb << 32) | (unsigned)(K - c));
        }
    }

    // Phase 7: completion handshake; last block inlines the finalize.
    __threadfence();
    __syncthreads();
    if (tid == 0) {
        unsigned ticket = atomicAdd(&g_done, 1u);
        s_isLast = (ticket == NCLS - 1);
        if (s_isLast) g_done = 0;    // sole accessor now; reset for next launch
    }
    __syncthreads();
    if (!s_isLast) return;

    // ---- Inline finalize (runs once, on the last-finishing block) ----
    int* flabel = reinterpret_cast<int*>(smask);     // alias, masks done

    {
        // atomicExch = coherent L2 read + self-resetting scratch
        unsigned long long kv = atomicExch(&g_rowkey[tid], 0ULL);
        unsigned sb = (unsigned)(kv >> 32);          // 0 if no winner
        flabel[tid] = kv ? (K - (int)(kv & 0xffffffffu)) : 0;
        skey[tid] = ((unsigned long long)(~sb) << 32) | (unsigned)tid;
    }
    __syncthreads();

    sort512(skey, tid);

    if (tid < MAX_PER_IMG) {
        unsigned long long kk = skey[tid];
        int top = (unsigned)kk;
        float sc = __uint_as_float(~(unsigned)(kk >> 32));
        int lab = flabel[top];
        bool valid = sc > SCORE_THRESH;
        float4 b = xform_box(rois, deltas, top, lab);

        float osc = valid ? sc : 0.0f;
        float bx1 = valid ? b.x : 0.0f;
        float by1 = valid ? b.y : 0.0f;
        float bx2 = valid ? b.z : 0.0f;
        float by2 = valid ? b.w : 0.0f;

        int base = tid * 5;
        if (base + 4 < out_size) {
            out[base + 0] = osc;
            out[base + 1] = bx1;
            out[base + 2] = by1;
            out[base + 3] = bx2;
            out[base + 4] = by2;
        }
        if (MAX_PER_IMG * 5 + tid < out_size) out[MAX_PER_IMG * 5 + tid] = (float)lab;
        if (MAX_PER_IMG * 6 + tid < out_size) out[MAX_PER_IMG * 6 + tid] = (float)top;
    }
}

// ---------------------------------------------------------------------------
extern "C" void kernel_launch(void* const* d_in, const int* in_sizes, int n_in,
                              void* d_out, int out_size) {
    const float* rois   = (const float*)d_in[0];
    const float* deltas = (const float*)d_in[1];
    const float* scores = (const float*)d_in[2];
    float* out = (float*)d_out;
    (void)in_sizes; (void)n_in;

    detect_kernel<<<NCLS, R>>>(rois, deltas, scores, out, out_size);
}

// round 17
// speedup vs baseline: 1.6039x; 1.1404x over previous
#include <cuda_runtime.h>
#include <cuda_bf16.h>
#include <math.h>

#define R 512
#define K 81
#define SCORE_THRESH 0.001f
#define MAX_PER_IMG 100
#define POST_NMS_TOPN 300
#define XFORM_CLIP 4.135166556742356f  /* log(1000/16) */
#define IM_W_M1 1332.0f
#define IM_H_M1 799.0f
#define NCLS 80                        /* classes 1..80 (class 0 always invalid) */

// ---- global scratch (zero-init at load; all self-resetting per launch) ----
__device__ unsigned           g_done;       // finalize ticket
__device__ unsigned long long g_rowkey[R]; // per-row argmax accumulator

// ---------------------------------------------------------------------------
__device__ __forceinline__ float4 xform_box(const float* __restrict__ rois,
                                            const float* __restrict__ deltas,
                                            int r, int k) {
    float4 roi = reinterpret_cast<const float4*>(rois)[r];
    float4 dl  = *reinterpret_cast<const float4*>(deltas + r * (4 * K) + 4 * k);

    float w  = roi.z - roi.x + 1.0f;
    float h  = roi.w - roi.y + 1.0f;
    float cx = roi.x + 0.5f * w;
    float cy = roi.y + 0.5f * h;

    float dx = dl.x / 10.0f;
    float dy = dl.y / 10.0f;
    float dw = fminf(dl.z / 5.0f, XFORM_CLIP);
    float dh = fminf(dl.w / 5.0f, XFORM_CLIP);

    float pcx = dx * w + cx;
    float pcy = dy * h + cy;
    float pw  = expf(dw) * w;
    float ph  = expf(dh) * h;

    float ox1 = fminf(fmaxf(pcx - 0.5f * pw, 0.0f), IM_W_M1);
    float oy1 = fminf(fmaxf(pcy - 0.5f * ph, 0.0f), IM_H_M1);
    float ox2 = fminf(fmaxf(pcx + 0.5f * pw - 1.0f, 0.0f), IM_W_M1);
    float oy2 = fminf(fmaxf(pcy + 0.5f * ph - 1.0f, 0.0f), IM_H_M1);
    return make_float4(ox1, oy1, ox2, oy2);
}

// ---------------------------------------------------------------------------
__device__ __forceinline__ unsigned long long cswap_shfl(unsigned long long key,
                                                         int tid, int kk, int j) {
    unsigned long long pk = __shfl_xor_sync(0xffffffffu, key, j);
    bool asc   = ((tid & kk) == 0);
    bool lower = ((tid & j) == 0);
    bool cmp   = key > pk;
    bool take  = ((cmp == asc) == lower);
    return take ? pk : key;
}

__device__ __forceinline__ void sort512(unsigned long long* skey, int tid) {
    unsigned long long key = skey[tid];
#pragma unroll
    for (int kk = 2; kk <= 32; kk <<= 1)
#pragma unroll
        for (int j = kk >> 1; j > 0; j >>= 1)
            key = cswap_shfl(key, tid, kk, j);
    skey[tid] = key;
    __syncthreads();
#pragma unroll
    for (int kk = 64; kk <= 512; kk <<= 1) {
        for (int j = kk >> 1; j >= 32; j >>= 1) {
            int ixj = tid ^ j;
            if (ixj > tid) {
                bool up = ((tid & kk) == 0);
                unsigned long long a = skey[tid], b = skey[ixj];
                if ((a > b) == up) { skey[tid] = b; skey[ixj] = a; }
            }
            __syncthreads();
        }
        key = skey[tid];
#pragma unroll
        for (int j = 16; j > 0; j >>= 1)
            key = cswap_shfl(key, tid, kk, j);
        skey[tid] = key;
        __syncthreads();
    }
}

// ---------------------------------------------------------------------------
// One block per class, 512 threads. Warp-specialized mask/scan overlap:
//   warps 1..15: produce suppression mask row-chunk by row-chunk
//   warp 0:      greedy-scan chunk ch as soon as its 15 producer arrivals land
// Boxes republished with +1 folded into z,w (exact: coords < 2^11), so the
// IoU inner loop does one FSUB per axis instead of FSUB+FADD.
// ---------------------------------------------------------------------------
__global__ __launch_bounds__(R, 1) void detect_kernel(const float* __restrict__ rois,
                                                      const float* __restrict__ deltas,
                                                      const float* __restrict__ scores,
                                                      float* __restrict__ out,
                                                      int out_size) {
    const int c   = blockIdx.x + 1;
    const int tid = threadIdx.x;

    // 16B alignment REQUIRED: smask head aliased as float4*.
    __shared__ __align__(16) unsigned smask[R * 16];   // 32 KB
    __shared__ unsigned long long skey[R];             // 4 KB
    __shared__ float4 sboxS[R];                        // 8 KB  sorted boxes (z,w pre-offset +1)
    __shared__ float  sareaS[R];                       // 2 KB  sorted areas
    __shared__ unsigned skeepw[16];
    __shared__ unsigned s_arrive[16];                  // per-chunk producer arrivals
    __shared__ int s_isLast;
    float4* sboxO  = reinterpret_cast<float4*>(smask);            // 8 KB alias
    float*  sareaO = reinterpret_cast<float*>(smask + 2048 * 2);  // alias @16KB

    // Phase 1: box + stable sort key for this row
    {
        float4 b = xform_box(rois, deltas, tid, c);
        sboxO[tid]  = b;
        sareaO[tid] = (b.z - b.x + 1.0f) * (b.w - b.y + 1.0f);
        unsigned sb = __float_as_uint(scores[tid * K + c]);
        skey[tid] = ((unsigned long long)(~sb) << 32) | (unsigned)tid;
    }
    __syncthreads();

    // Phase 2: sort (ascending uint64 => score desc, idx asc)
    sort512(skey, tid);

    // Phase 3: gather boxes into sorted order; fold +1 into z,w (exact).
    {
        int oi = (unsigned)skey[tid];
        float4 bi = sboxO[oi];
        float  ai = sareaO[oi];
        __syncthreads();                 // gathers done before alias reuse
        sboxS[tid]  = make_float4(bi.x, bi.y, bi.z + 1.0f, bi.w + 1.0f);
        sareaS[tid] = ai;
        if (tid < 16) s_arrive[tid] = 0u;
    }
    __syncthreads();

    // Phase 4+5 overlapped: producers (warps 1-15) & scanner (warp 0)
    const int wid  = tid >> 5;
    const int lane = tid & 31;

    if (wid != 0) {
        // ---------------- producers: chunk-ordered mask ----------------
        const int q = wid - 1;                    // 0..14
        for (int ch = 0; ch < 16; ++ch) {
            const float4 bi = sboxS[ch * 32 + lane];
            const float  ai = sareaS[ch * 32 + lane];
            for (int w = ch + q; w < 16; w += 15) {
                unsigned bits = 0;
#pragma unroll
                for (int b = 0; b < 32; ++b) {
                    int j = (w << 5) | b;
                    float4 bj = sboxS[j];            // broadcast across warp
                    float  aj = sareaS[j];
                    // z,w carry +1 already: one FSUB per axis
                    float iw = fmaxf(fminf(bi.z, bj.z) - fmaxf(bi.x, bj.x), 0.0f);
                    float ih = fmaxf(fminf(bi.w, bj.w) - fmaxf(bi.y, bj.y), 0.0f);
                    float inter = iw * ih;
                    float uni = ai + aj - inter;     // > 0 always
                    if (inter + inter > uni) bits |= (1u << b);   // iou > 0.5
                }
                smask[(ch * 32 + lane) * 16 + w] = bits;
            }
            __threadfence_block();                   // publish chunk words
            if (lane == 0) atomicAdd(&s_arrive[ch], 1u);
        }
    } else {
        // ---------------- scanner: greedy scan, chunk-gated -------------
        unsigned remv = 0, kw = 0;
        for (int ch = 0; ch < 16; ++ch) {
            if (lane == 0) {
                while (*(volatile unsigned*)&s_arrive[ch] < 15u) __nanosleep(32);
            }
            __syncwarp();
            __threadfence_block();                   // acquire chunk words

            unsigned kwc = 0;
            if (lane == ch) {
                unsigned diag[32];
#pragma unroll
                for (int j = 0; j < 32; ++j)
                    diag[j] = smask[(ch * 32 + j) * 16 + ch];
#pragma unroll
                for (int j = 0; j < 32; ++j) {
                    unsigned s = (unsigned)(((int)(remv << (31 - j))) >> 31);
                    remv |= diag[j] & ~s & (0xFFFFFFFEu << j);
                }
                kwc = ~remv;                // live set of this chunk
                kw = kwc;
            }
            kwc = __shfl_sync(0xffffffffu, kwc, ch);
            if (lane > ch && lane < 16) {
#pragma unroll
                for (int j = 0; j < 32; ++j) {
                    unsigned live = (unsigned)(((int)(kwc << (31 - j))) >> 31);
                    remv |= smask[(ch * 32 + j) * 16 + lane] & live;
                }
            }
        }
        // POST_NMS_TOPN clamp: keep first 300 kept (sorted order)
        int cnt = (lane < 16) ? __popc(kw) : 0;
        int incl = cnt;
        for (int off = 1; off < 16; off <<= 1) {
            int v = __shfl_up_sync(0xffffffffu, incl, off);
            if (lane >= off) incl += v;
        }
        int excl = incl - cnt;
        if (lane < 16) {
            if (excl >= POST_NMS_TOPN) {
                kw = 0;
            } else if (excl + cnt > POST_NMS_TOPN) {
                int allowed = POST_NMS_TOPN - excl;
                while (cnt > allowed) {
                    int hb = 31 - __clz(kw);
                    kw &= ~(1u << hb);
                    --cnt;
                }
            }
            skeepw[lane] = kw;
        }
    }
    __syncthreads();

    // Phase 6: class validity + per-row argmax accumulation.
    // key = score_bits<<32 | (K - c): max => highest score, ties => smallest
    // class = first-occurrence argmax. Bit-exact score carried through.
    {
        float maxsc = __uint_as_float(~(unsigned)(skey[0] >> 32));
        bool cvalid = maxsc > SCORE_THRESH;          // c >= 1 by construction
        unsigned long long kk = skey[tid];
        bool kept = (skeepw[tid >> 5] >> (tid & 31)) & 1u;
        if (cvalid && kept) {
            unsigned sb = ~(unsigned)(kk >> 32);     // raw score bits (> 0)
            int orig = (unsigned)kk;
            atomicMax(&g_rowkey[orig],
                      ((unsigned long long)sb << 32) | (unsigned)(K - c));
        }
    }

    // Phase 7: completion handshake; last block inlines the finalize.
    __threadfence();
    __syncthreads();
    if (tid == 0) {
        unsigned ticket = atomicAdd(&g_done, 1u);
        s_isLast = (ticket == NCLS - 1);
        if (s_isLast) g_done = 0;    // sole accessor now; reset for next launch
    }
    __syncthreads();
    if (!s_isLast) return;

    // ---- Inline finalize (runs once, on the last-finishing block) ----
    int* flabel = reinterpret_cast<int*>(smask);     // alias, masks done

    {
        // atomicExch = coherent L2 read + self-resetting scratch
        unsigned long long kv = atomicExch(&g_rowkey[tid], 0ULL);
        unsigned sb = (unsigned)(kv >> 32);          // 0 if no winner
        flabel[tid] = kv ? (K - (int)(kv & 0xffffffffu)) : 0;
        skey[tid] = ((unsigned long long)(~sb) << 32) | (unsigned)tid;
    }
    __syncthreads();

    sort512(skey, tid);

    if (tid < MAX_PER_IMG) {
        unsigned long long kk = skey[tid];
        int top = (unsigned)kk;
        float sc = __uint_as_float(~(unsigned)(kk >> 32));
        int lab = flabel[top];
        bool valid = sc > SCORE_THRESH;
        float4 b = xform_box(rois, deltas, top, lab);

        float osc = valid ? sc : 0.0f;
        float bx1 = valid ? b.x : 0.0f;
        float by1 = valid ? b.y : 0.0f;
        float bx2 = valid ? b.z : 0.0f;
        float by2 = valid ? b.w : 0.0f;

        int base = tid * 5;
        if (base + 4 < out_size) {
            out[base + 0] = osc;
            out[base + 1] = bx1;
            out[base + 2] = by1;
            out[base + 3] = bx2;
            out[base + 4] = by2;
        }
        if (MAX_PER_IMG * 5 + tid < out_size) out[MAX_PER_IMG * 5 + tid] = (float)lab;
        if (MAX_PER_IMG * 6 + tid < out_size) out[MAX_PER_IMG * 6 + tid] = (float)top;
    }
}

// ---------------------------------------------------------------------------
extern "C" void kernel_launch(void* const* d_in, const int* in_sizes, int n_in,
                              void* d_out, int out_size) {
    const float* rois   = (const float*)d_in[0];
    const float* deltas = (const float*)d_in[1];
    const float* scores = (const float*)d_in[2];
    float* out = (float*)d_out;
    (void)in_sizes; (void)n_in;

    detect_kernel<<<NCLS, R>>>(rois, deltas, scores, out, out_size);
}